// round 8
// baseline (speedup 1.0000x reference)
#include <cuda_runtime.h>
#include <math.h>

#define NPTS 16384
#define DIM  64
#define NC   9
#define CAP  16384   // per-class region capacity (worst case: all points one class)
#define IT   128     // i-tile for KB
#define JT   64      // j-tile rows staged in smem
#define NB3  592     // KB grid
#define KAB  128     // KA blocks (128 x 128 = 16384 threads)

// ---- device scratch ----
__device__ float g_cf[8 * CAP * DIM];    // class-region normalized feats (32 MB)
__device__ int   g_fill[NC] = {0, 0, CAP, 2*CAP, 3*CAP, 4*CAP, 5*CAP, 6*CAP, 7*CAP};
__device__ float g_sum[NC * DIM];        // per-class normalized-feature sums
__device__ float g_cross[NC * NC];       // ordered relu(dot) sums (2x unordered)
__device__ unsigned g_t3;

// ---- KA: fused classify + normalize + scatter (no global sync needed) ----
__global__ void __launch_bounds__(128) ka_classify_scatter(
        const int* __restrict__ labels,
        const float* __restrict__ feats,
        const float* __restrict__ scores) {
    int tid = threadIdx.x;
    int lane = tid & 31;
    int p = blockIdx.x * 128 + tid;

    // classify: 9 direct loads (warp rows adjacent -> coalesced line reuse)
    const float* sr = scores + p * NC;
    float sv[NC];
    #pragma unroll
    for (int c = 0; c < NC; c++) sv[c] = __ldg(&sr[c]);
    float mv = sv[0]; int mi = 0;
    #pragma unroll
    for (int c = 1; c < NC; c++) if (sv[c] > mv) { mv = sv[c]; mi = c; }
    float e = 0.f;
    #pragma unroll
    for (int c = 0; c < NC; c++) e += expf(sv[c] - mv);
    float pmax = 1.0f / e;

    int lab = labels[p];
    int cls = (lab == mi && pmax >= 0.5f && lab >= 1) ? lab : 0;

    // warp-cooperative scatter of the valid points in this warp (~3 avg)
    unsigned bal = __ballot_sync(0xffffffffu, cls > 0);
    while (bal) {
        int src = __ffs(bal) - 1;
        bal &= bal - 1;
        int pc = __shfl_sync(0xffffffffu, cls, src);
        int pp = __shfl_sync(0xffffffffu, p, src);

        float x0 = feats[pp * DIM + lane];
        float x1 = feats[pp * DIM + 32 + lane];
        float ss = x0 * x0 + x1 * x1;
        #pragma unroll
        for (int o = 16; o > 0; o >>= 1) ss += __shfl_xor_sync(0xffffffffu, ss, o);
        float inv = 1.0f / fmaxf(sqrtf(ss), 1e-12f);
        float f0 = x0 * inv, f1 = x1 * inv;

        int slot;
        if (lane == 0) slot = atomicAdd(&g_fill[pc], 1);
        slot = __shfl_sync(0xffffffffu, slot, 0);

        g_cf[slot * DIM + lane]      = f0;
        g_cf[slot * DIM + 32 + lane] = f1;
        atomicAdd(&g_sum[pc * DIM + lane],      f0);
        atomicAdd(&g_sum[pc * DIM + 32 + lane], f1);
    }
}

// ---- KB: full-symmetric pairwise relu(dot) over virtual compact index ----
__global__ void __launch_bounds__(128, 4) kb_pairs(float* __restrict__ out) {
    __shared__ float4 Js[JT][16];
    __shared__ float  scross[NC * NC];
    __shared__ int    s_pre[NC + 1];   // virtual-space class prefix (class 1..8)
    __shared__ int    s_base[NC];      // physical region bases
    __shared__ int    jphys[JT];

    int tid = threadIdx.x;
    if (tid < NC * NC) scross[tid] = 0.f;
    if (tid == 0) {
        int acc = 0;
        #pragma unroll
        for (int c = 1; c < NC; c++) {
            int base = (c - 1) * CAP;
            s_base[c] = base;
            s_pre[c] = acc;
            acc += g_fill[c] - base;   // cnt[c]
        }
        s_pre[NC] = acc;               // nvalid
    }
    __syncthreads();

    int nv = s_pre[NC];
    int nit = (nv + IT - 1) / IT;
    int njt = (nv + JT - 1) / JT;
    int njobs = nit * njt;

    const float4* cf4 = (const float4*)g_cf;

    for (int job = blockIdx.x; job < njobs; job += NB3) {
        int it = job / njt, jt = job - it * njt;
        int jb = jt * JT;

        // map my i-row virtual -> physical + class
        int v = it * IT + tid;
        int ci = 0, iphys = 0;
        {
            int c = 1;
            #pragma unroll
            for (int cc = 2; cc < NC; cc++) if (v >= s_pre[cc]) c = cc;
            iphys = s_base[c] + (v - s_pre[c]);
            ci = (v < nv) ? c : 0;
        }
        float4 row[16];
        #pragma unroll
        for (int c4 = 0; c4 < 16; c4++) row[c4] = cf4[iphys * 16 + c4];

        __syncthreads();   // protect Js/jphys from previous job's readers
        if (tid < JT) {
            int jv = jb + tid;
            int c = 1;
            #pragma unroll
            for (int cc = 2; cc < NC; cc++) if (jv >= s_pre[cc]) c = cc;
            jphys[tid] = (jv < nv) ? (s_base[c] + (jv - s_pre[c])) : 0;
        }
        __syncthreads();
        for (int q = tid; q < JT * 16; q += 128)
            Js[q >> 4][q & 15] = cf4[jphys[q >> 4] * 16 + (q & 15)];
        __syncthreads();

        if (ci > 0) {
            #pragma unroll
            for (int c = 1; c < NC; c++) {
                if (c == ci) continue;
                int rs = max(s_pre[c] - jb, 0);
                int re = min(s_pre[c + 1] - jb, JT);
                if (rs >= re) continue;
                float rsum = 0.f;
                int j = rs;
                for (; j + 1 < re; j += 2) {
                    float d0x = 0.f, d0y = 0.f, d0z = 0.f, d0w = 0.f;
                    float d1x = 0.f, d1y = 0.f, d1z = 0.f, d1w = 0.f;
                    #pragma unroll
                    for (int c4 = 0; c4 < 16; c4++) {
                        float4 b0 = Js[j][c4];
                        float4 b1 = Js[j + 1][c4];
                        d0x += row[c4].x * b0.x; d0y += row[c4].y * b0.y;
                        d0z += row[c4].z * b0.z; d0w += row[c4].w * b0.w;
                        d1x += row[c4].x * b1.x; d1y += row[c4].y * b1.y;
                        d1z += row[c4].z * b1.z; d1w += row[c4].w * b1.w;
                    }
                    rsum += fmaxf((d0x + d0y) + (d0z + d0w), 0.f)
                          + fmaxf((d1x + d1y) + (d1z + d1w), 0.f);
                }
                if (j < re) {
                    float dx = 0.f, dy = 0.f, dz = 0.f, dw = 0.f;
                    #pragma unroll
                    for (int c4 = 0; c4 < 16; c4++) {
                        float4 b = Js[j][c4];
                        dx += row[c4].x * b.x; dy += row[c4].y * b.y;
                        dz += row[c4].z * b.z; dw += row[c4].w * b.w;
                    }
                    rsum += fmaxf((dx + dy) + (dz + dw), 0.f);
                }
                if (rsum > 0.f) {
                    int lo = min(ci, c), hi = max(ci, c);
                    atomicAdd(&scross[lo * NC + hi], rsum);
                }
            }
        }
    }
    __syncthreads();
    if (tid < NC * NC && scross[tid] != 0.f) atomicAdd(&g_cross[tid], scross[tid]);

    // ---- last-block finalize + reset for next graph replay ----
    __shared__ bool is_last;
    __threadfence();
    __syncthreads();
    if (tid == 0) is_last = (atomicAdd(&g_t3, 1u) == NB3 - 1);
    __syncthreads();
    if (!is_last) return;
    __threadfence();

    __shared__ float red[128];
    float acc = 0.f;
    if (tid >= 1 && tid < NC) {
        float cnt = (float)(s_pre[tid + 1] - s_pre[tid]);
        float quad = 0.f;
        #pragma unroll
        for (int d = 0; d < DIM; d++) {
            float vv = g_sum[tid * DIM + d];
            quad += vv * vv;
        }
        float npairs = cnt * (cnt - 1.0f) * 0.5f;
        if (npairs > 0.f)
            acc += 1.0f - ((quad - cnt) * 0.5f) / npairs;
    }
    for (int idx = tid; idx < NC * NC; idx += 128) {
        int a = idx / NC, b = idx % NC;
        if (a >= 1 && b > a) {
            float ca = (float)(s_pre[a + 1] - s_pre[a]);
            float cb = (float)(s_pre[b + 1] - s_pre[b]);
            float den = ca * cb;
            // g_cross holds ordered (both-direction) sums = 2x unordered
            if (den > 0.f) acc += 0.5f * g_cross[a * NC + b] / den;
        }
    }
    red[tid] = acc;
    __syncthreads();
    #pragma unroll
    for (int o = 64; o > 0; o >>= 1) {
        if (tid < o) red[tid] += red[tid + o];
        __syncthreads();
    }
    if (tid == 0) out[0] = red[0];

    // reset for next replay
    __syncthreads();
    if (tid >= 1 && tid < NC) g_fill[tid] = (tid - 1) * CAP;
    if (tid < NC * NC) g_cross[tid] = 0.f;
    for (int i = tid; i < NC * DIM; i += 128) g_sum[i] = 0.f;
    if (tid == 0) g_t3 = 0;
}

extern "C" void kernel_launch(void* const* d_in, const int* in_sizes, int n_in,
                              void* d_out, int out_size) {
    const int*   labels = nullptr;
    const float* feats  = nullptr;
    const float* scores = nullptr;
    for (int i = 0; i < n_in; i++) {
        if (in_sizes[i] == NPTS)            labels = (const int*)d_in[i];
        else if (in_sizes[i] == NPTS * DIM) feats  = (const float*)d_in[i];
        else if (in_sizes[i] == NPTS * NC)  scores = (const float*)d_in[i];
    }
    float* out = (float*)d_out;

    ka_classify_scatter<<<KAB, 128>>>(labels, feats, scores);
    kb_pairs<<<NB3, 128>>>(out);
}

// round 9
// speedup vs baseline: 1.1677x; 1.1677x over previous
#include <cuda_runtime.h>
#include <math.h>

#define NPTS 16384
#define DIM  64
#define NC   9
#define CAP  16384   // per-class region capacity
#define IT   128     // i-tile for KB
#define JT   64      // j-tile rows staged in smem (JT = IT/2 required)
#define NB3  592     // KB grid
#define KAB  128     // KA blocks (128 x 128 = 16384 threads)

// ---- device scratch ----
__device__ float g_cf[8 * CAP * DIM];    // class-region normalized feats
__device__ int   g_fill[NC] = {0, 0, CAP, 2*CAP, 3*CAP, 4*CAP, 5*CAP, 6*CAP, 7*CAP};
__device__ float g_sum[NC * DIM];        // per-class normalized-feature sums
__device__ float g_cross[NC * NC];       // UNORDERED relu(dot) sums per class pair
__device__ unsigned g_t3;

// ---- KA: fused classify + normalize + scatter ----
__global__ void __launch_bounds__(128) ka_classify_scatter(
        const int* __restrict__ labels,
        const float* __restrict__ feats,
        const float* __restrict__ scores) {
    int tid = threadIdx.x;
    int lane = tid & 31;
    int p = blockIdx.x * 128 + tid;

    const float* sr = scores + p * NC;
    float sv[NC];
    #pragma unroll
    for (int c = 0; c < NC; c++) sv[c] = __ldg(&sr[c]);
    float mv = sv[0]; int mi = 0;
    #pragma unroll
    for (int c = 1; c < NC; c++) if (sv[c] > mv) { mv = sv[c]; mi = c; }
    float e = 0.f;
    #pragma unroll
    for (int c = 0; c < NC; c++) e += expf(sv[c] - mv);
    float pmax = 1.0f / e;

    int lab = labels[p];
    int cls = (lab == mi && pmax >= 0.5f && lab >= 1) ? lab : 0;

    unsigned bal = __ballot_sync(0xffffffffu, cls > 0);
    while (bal) {
        int src = __ffs(bal) - 1;
        bal &= bal - 1;
        int pc = __shfl_sync(0xffffffffu, cls, src);
        int pp = __shfl_sync(0xffffffffu, p, src);

        float x0 = feats[pp * DIM + lane];
        float x1 = feats[pp * DIM + 32 + lane];
        float ss = x0 * x0 + x1 * x1;
        #pragma unroll
        for (int o = 16; o > 0; o >>= 1) ss += __shfl_xor_sync(0xffffffffu, ss, o);
        float inv = 1.0f / fmaxf(sqrtf(ss), 1e-12f);
        float f0 = x0 * inv, f1 = x1 * inv;

        int slot;
        if (lane == 0) slot = atomicAdd(&g_fill[pc], 1);
        slot = __shfl_sync(0xffffffffu, slot, 0);

        g_cf[slot * DIM + lane]      = f0;
        g_cf[slot * DIM + 32 + lane] = f1;
        atomicAdd(&g_sum[pc * DIM + lane],      f0);
        atomicAdd(&g_sum[pc * DIM + 32 + lane], f1);
    }
}

// ---- KB: triangular pairwise relu(dot); i-rows in registers, NO spills ----
__global__ void __launch_bounds__(128, 2) kb_pairs(float* __restrict__ out) {
    __shared__ float4 Js[JT][16];
    __shared__ float  scross[NC * NC];
    __shared__ int    s_pre[NC + 1];
    __shared__ int    s_base[NC];
    __shared__ int    jphys[JT];

    int tid = threadIdx.x;
    if (tid < NC * NC) scross[tid] = 0.f;
    if (tid == 0) {
        int acc = 0;
        #pragma unroll
        for (int c = 1; c < NC; c++) {
            int base = (c - 1) * CAP;
            s_base[c] = base;
            s_pre[c] = acc;
            acc += g_fill[c] - base;
        }
        s_pre[NC] = acc;
    }
    __syncthreads();

    int nv = s_pre[NC];
    int nit = (nv + IT - 1) / IT;
    int njt = (nv + JT - 1) / JT;
    // triangular job set: (it, jt) with jt >= 2*it  (valid since JT == IT/2)
    int njobs = nit * njt - nit * (nit - 1);

    const float4* cf4 = (const float4*)g_cf;

    for (int job = blockIdx.x; job < njobs; job += NB3) {
        // decode job -> (it, jt): counts per it are (njt - 2*it)
        int it = 0, rem = job;
        while (rem >= njt - 2 * it) { rem -= njt - 2 * it; it++; }
        int jt = 2 * it + rem;
        int jb = jt * JT;

        int iv = it * IT + tid;
        int ci = 0, iphys = 0;
        {
            int c = 1;
            #pragma unroll
            for (int cc = 2; cc < NC; cc++) if (iv >= s_pre[cc]) c = cc;
            iphys = s_base[c] + (iv - s_pre[c]);
            ci = (iv < nv) ? c : 0;
        }
        float4 row[16];
        #pragma unroll
        for (int c4 = 0; c4 < 16; c4++) row[c4] = cf4[iphys * 16 + c4];

        // only count pairs with jv > iv (strict upper triangle)
        int jmin = iv - jb;   // process local j only if j > jmin

        __syncthreads();
        if (tid < JT) {
            int jv = jb + tid;
            int c = 1;
            #pragma unroll
            for (int cc = 2; cc < NC; cc++) if (jv >= s_pre[cc]) c = cc;
            jphys[tid] = (jv < nv) ? (s_base[c] + (jv - s_pre[c])) : 0;
        }
        __syncthreads();
        for (int q = tid; q < JT * 16; q += 128)
            Js[q >> 4][q & 15] = cf4[jphys[q >> 4] * 16 + (q & 15)];
        __syncthreads();

        if (ci > 0) {
            #pragma unroll
            for (int c = 1; c < NC; c++) {
                if (c == ci) continue;
                int rs = max(s_pre[c] - jb, 0);
                int re = min(s_pre[c + 1] - jb, JT);
                if (rs >= re) continue;
                float rsum = 0.f;
                int j = rs;
                for (; j + 1 < re; j += 2) {
                    float d0x = 0.f, d0y = 0.f, d0z = 0.f, d0w = 0.f;
                    float d1x = 0.f, d1y = 0.f, d1z = 0.f, d1w = 0.f;
                    #pragma unroll
                    for (int c4 = 0; c4 < 16; c4++) {
                        float4 b0 = Js[j][c4];
                        float4 b1 = Js[j + 1][c4];
                        d0x += row[c4].x * b0.x; d0y += row[c4].y * b0.y;
                        d0z += row[c4].z * b0.z; d0w += row[c4].w * b0.w;
                        d1x += row[c4].x * b1.x; d1y += row[c4].y * b1.y;
                        d1z += row[c4].z * b1.z; d1w += row[c4].w * b1.w;
                    }
                    float s0 = fmaxf((d0x + d0y) + (d0z + d0w), 0.f);
                    float s1 = fmaxf((d1x + d1y) + (d1z + d1w), 0.f);
                    if (j > jmin)     rsum += s0;
                    if (j + 1 > jmin) rsum += s1;
                }
                if (j < re) {
                    float dx = 0.f, dy = 0.f, dz = 0.f, dw = 0.f;
                    #pragma unroll
                    for (int c4 = 0; c4 < 16; c4++) {
                        float4 b = Js[j][c4];
                        dx += row[c4].x * b.x; dy += row[c4].y * b.y;
                        dz += row[c4].z * b.z; dw += row[c4].w * b.w;
                    }
                    if (j > jmin) rsum += fmaxf((dx + dy) + (dz + dw), 0.f);
                }
                if (rsum > 0.f) {
                    int lo = min(ci, c), hi = max(ci, c);
                    atomicAdd(&scross[lo * NC + hi], rsum);
                }
            }
        }
    }
    __syncthreads();
    if (tid < NC * NC && scross[tid] != 0.f) atomicAdd(&g_cross[tid], scross[tid]);

    // ---- last-block finalize + reset for next graph replay ----
    __shared__ bool is_last;
    __threadfence();
    __syncthreads();
    if (tid == 0) is_last = (atomicAdd(&g_t3, 1u) == NB3 - 1);
    __syncthreads();
    if (!is_last) return;
    __threadfence();

    __shared__ float red[128];
    float acc = 0.f;
    if (tid >= 1 && tid < NC) {
        float cnt = (float)(s_pre[tid + 1] - s_pre[tid]);
        float quad = 0.f;
        #pragma unroll
        for (int d = 0; d < DIM; d++) {
            float vv = g_sum[tid * DIM + d];
            quad += vv * vv;
        }
        float npairs = cnt * (cnt - 1.0f) * 0.5f;
        if (npairs > 0.f)
            acc += 1.0f - ((quad - cnt) * 0.5f) / npairs;
    }
    for (int idx = tid; idx < NC * NC; idx += 128) {
        int a = idx / NC, b = idx % NC;
        if (a >= 1 && b > a) {
            float ca = (float)(s_pre[a + 1] - s_pre[a]);
            float cb = (float)(s_pre[b + 1] - s_pre[b]);
            float den = ca * cb;
            // g_cross already holds unordered-once sums
            if (den > 0.f) acc += g_cross[a * NC + b] / den;
        }
    }
    red[tid] = acc;
    __syncthreads();
    #pragma unroll
    for (int o = 64; o > 0; o >>= 1) {
        if (tid < o) red[tid] += red[tid + o];
        __syncthreads();
    }
    if (tid == 0) out[0] = red[0];

    // reset for next replay
    __syncthreads();
    if (tid >= 1 && tid < NC) g_fill[tid] = (tid - 1) * CAP;
    if (tid < NC * NC) g_cross[tid] = 0.f;
    for (int i = tid; i < NC * DIM; i += 128) g_sum[i] = 0.f;
    if (tid == 0) g_t3 = 0;
}

extern "C" void kernel_launch(void* const* d_in, const int* in_sizes, int n_in,
                              void* d_out, int out_size) {
    const int*   labels = nullptr;
    const float* feats  = nullptr;
    const float* scores = nullptr;
    for (int i = 0; i < n_in; i++) {
        if (in_sizes[i] == NPTS)            labels = (const int*)d_in[i];
        else if (in_sizes[i] == NPTS * DIM) feats  = (const float*)d_in[i];
        else if (in_sizes[i] == NPTS * NC)  scores = (const float*)d_in[i];
    }
    float* out = (float*)d_out;

    ka_classify_scatter<<<KAB, 128>>>(labels, feats, scores);
    kb_pairs<<<NB3, 128>>>(out);
}

// round 10
// speedup vs baseline: 1.2401x; 1.0620x over previous
#include <cuda_runtime.h>
#include <math.h>

#define NPTS 16384
#define DIM  64
#define NC   9
#define CAP  16384   // per-class region capacity
#define IT   128     // i-tile for KB
#define JT   32      // j-tile rows staged in smem (RATIO = IT/JT = 4)
#define RATIO 4
#define NB3  592     // KB grid
#define KAB  128     // KA blocks (128 x 128 = 16384 threads)

// ---- device scratch ----
__device__ float g_cf[8 * CAP * DIM];    // class-region normalized feats
__device__ int   g_fill[NC] = {0, 0, CAP, 2*CAP, 3*CAP, 4*CAP, 5*CAP, 6*CAP, 7*CAP};
__device__ float g_sum[NC * DIM];        // per-class normalized-feature sums
__device__ float g_cross[NC * NC];       // UNORDERED relu(dot) sums per class pair
__device__ unsigned g_t3;

// ---- KA: fused classify + normalize + scatter ----
__global__ void __launch_bounds__(128) ka_classify_scatter(
        const int* __restrict__ labels,
        const float* __restrict__ feats,
        const float* __restrict__ scores) {
    int tid = threadIdx.x;
    int lane = tid & 31;
    int p = blockIdx.x * 128 + tid;

    const float* sr = scores + p * NC;
    float sv[NC];
    #pragma unroll
    for (int c = 0; c < NC; c++) sv[c] = __ldg(&sr[c]);
    float mv = sv[0]; int mi = 0;
    #pragma unroll
    for (int c = 1; c < NC; c++) if (sv[c] > mv) { mv = sv[c]; mi = c; }
    float e = 0.f;
    #pragma unroll
    for (int c = 0; c < NC; c++) e += expf(sv[c] - mv);
    float pmax = 1.0f / e;

    int lab = labels[p];
    int cls = (lab == mi && pmax >= 0.5f && lab >= 1) ? lab : 0;

    unsigned bal = __ballot_sync(0xffffffffu, cls > 0);
    while (bal) {
        int src = __ffs(bal) - 1;
        bal &= bal - 1;
        int pc = __shfl_sync(0xffffffffu, cls, src);
        int pp = __shfl_sync(0xffffffffu, p, src);

        float x0 = feats[pp * DIM + lane];
        float x1 = feats[pp * DIM + 32 + lane];
        float ss = x0 * x0 + x1 * x1;
        #pragma unroll
        for (int o = 16; o > 0; o >>= 1) ss += __shfl_xor_sync(0xffffffffu, ss, o);
        float inv = 1.0f / fmaxf(sqrtf(ss), 1e-12f);
        float f0 = x0 * inv, f1 = x1 * inv;

        int slot;
        if (lane == 0) slot = atomicAdd(&g_fill[pc], 1);
        slot = __shfl_sync(0xffffffffu, slot, 0);

        g_cf[slot * DIM + lane]      = f0;
        g_cf[slot * DIM + 32 + lane] = f1;
        atomicAdd(&g_sum[pc * DIM + lane],      f0);
        atomicAdd(&g_sum[pc * DIM + 32 + lane], f1);
    }
}

// ---- KB: triangular pairwise relu(dot); i-rows in registers ----
__global__ void __launch_bounds__(128, 3) kb_pairs(float* __restrict__ out) {
    __shared__ float4 Js[JT][16];
    __shared__ float  scross[NC * NC];
    __shared__ int    s_pre[NC + 1];
    __shared__ int    s_base[NC];
    __shared__ int    jphys[JT];

    int tid = threadIdx.x;
    if (tid < NC * NC) scross[tid] = 0.f;
    if (tid == 0) {
        int acc = 0;
        #pragma unroll
        for (int c = 1; c < NC; c++) {
            int base = (c - 1) * CAP;
            s_base[c] = base;
            s_pre[c] = acc;
            acc += g_fill[c] - base;
        }
        s_pre[NC] = acc;
    }
    __syncthreads();

    int nv = s_pre[NC];
    int nit = (nv + IT - 1) / IT;
    int njt = (nv + JT - 1) / JT;
    // triangular job set: (it, jt) with jt >= RATIO*it
    int njobs = nit * njt - RATIO * nit * (nit - 1) / 2;

    const float4* cf4 = (const float4*)g_cf;

    for (int job = blockIdx.x; job < njobs; job += NB3) {
        int it = 0, rem = job;
        while (rem >= njt - RATIO * it) { rem -= njt - RATIO * it; it++; }
        int jt = RATIO * it + rem;
        int jb = jt * JT;

        int iv = it * IT + tid;
        int ci = 0, iphys = 0;
        {
            int c = 1;
            #pragma unroll
            for (int cc = 2; cc < NC; cc++) if (iv >= s_pre[cc]) c = cc;
            iphys = s_base[c] + (iv - s_pre[c]);
            ci = (iv < nv) ? c : 0;
        }
        float4 row[16];
        #pragma unroll
        for (int c4 = 0; c4 < 16; c4++) row[c4] = cf4[iphys * 16 + c4];

        int jmin = iv - jb;   // count local j only if j > jmin

        __syncthreads();
        if (tid < JT) {
            int jv = jb + tid;
            int c = 1;
            #pragma unroll
            for (int cc = 2; cc < NC; cc++) if (jv >= s_pre[cc]) c = cc;
            jphys[tid] = (jv < nv) ? (s_base[c] + (jv - s_pre[c])) : 0;
        }
        __syncthreads();
        #pragma unroll
        for (int q0 = 0; q0 < JT * 16; q0 += 128) {
            int q = q0 + tid;
            Js[q >> 4][q & 15] = cf4[jphys[q >> 4] * 16 + (q & 15)];
        }
        __syncthreads();

        if (ci > 0) {
            #pragma unroll
            for (int c = 1; c < NC; c++) {
                if (c == ci) continue;
                int rs = max(s_pre[c] - jb, 0);
                int re = min(s_pre[c + 1] - jb, JT);
                if (rs >= re) continue;
                float rsum = 0.f;
                for (int j = rs; j < re; j++) {
                    float dx = 0.f, dy = 0.f, dz = 0.f, dw = 0.f;
                    #pragma unroll
                    for (int c4 = 0; c4 < 16; c4++) {
                        float4 b = Js[j][c4];
                        dx += row[c4].x * b.x; dy += row[c4].y * b.y;
                        dz += row[c4].z * b.z; dw += row[c4].w * b.w;
                    }
                    float s = fmaxf((dx + dy) + (dz + dw), 0.f);
                    if (j > jmin) rsum += s;
                }
                if (rsum > 0.f) {
                    int lo = min(ci, c), hi = max(ci, c);
                    atomicAdd(&scross[lo * NC + hi], rsum);
                }
            }
        }
    }
    __syncthreads();
    if (tid < NC * NC && scross[tid] != 0.f) atomicAdd(&g_cross[tid], scross[tid]);

    // ---- last-block finalize + reset for next graph replay ----
    __shared__ bool is_last;
    __threadfence();
    __syncthreads();
    if (tid == 0) is_last = (atomicAdd(&g_t3, 1u) == NB3 - 1);
    __syncthreads();
    if (!is_last) return;
    __threadfence();

    __shared__ float red[128];
    float acc = 0.f;
    if (tid >= 1 && tid < NC) {
        float cnt = (float)(s_pre[tid + 1] - s_pre[tid]);
        float quad = 0.f;
        #pragma unroll
        for (int d = 0; d < DIM; d++) {
            float vv = g_sum[tid * DIM + d];
            quad += vv * vv;
        }
        float npairs = cnt * (cnt - 1.0f) * 0.5f;
        if (npairs > 0.f)
            acc += 1.0f - ((quad - cnt) * 0.5f) / npairs;
    }
    for (int idx = tid; idx < NC * NC; idx += 128) {
        int a = idx / NC, b = idx % NC;
        if (a >= 1 && b > a) {
            float ca = (float)(s_pre[a + 1] - s_pre[a]);
            float cb = (float)(s_pre[b + 1] - s_pre[b]);
            float den = ca * cb;
            if (den > 0.f) acc += g_cross[a * NC + b] / den;
        }
    }
    red[tid] = acc;
    __syncthreads();
    #pragma unroll
    for (int o = 64; o > 0; o >>= 1) {
        if (tid < o) red[tid] += red[tid + o];
        __syncthreads();
    }
    if (tid == 0) out[0] = red[0];

    // reset for next replay
    __syncthreads();
    if (tid >= 1 && tid < NC) g_fill[tid] = (tid - 1) * CAP;
    if (tid < NC * NC) g_cross[tid] = 0.f;
    for (int i = tid; i < NC * DIM; i += 128) g_sum[i] = 0.f;
    if (tid == 0) g_t3 = 0;
}

extern "C" void kernel_launch(void* const* d_in, const int* in_sizes, int n_in,
                              void* d_out, int out_size) {
    const int*   labels = nullptr;
    const float* feats  = nullptr;
    const float* scores = nullptr;
    for (int i = 0; i < n_in; i++) {
        if (in_sizes[i] == NPTS)            labels = (const int*)d_in[i];
        else if (in_sizes[i] == NPTS * DIM) feats  = (const float*)d_in[i];
        else if (in_sizes[i] == NPTS * NC)  scores = (const float*)d_in[i];
    }
    float* out = (float*)d_out;

    ka_classify_scatter<<<KAB, 128>>>(labels, feats, scores);
    kb_pairs<<<NB3, 128>>>(out);
}

// round 11
// speedup vs baseline: 1.3302x; 1.0727x over previous
#include <cuda_runtime.h>
#include <math.h>

#define NPTS 16384
#define DIM  64
#define NC   9
#define CAP  16384   // per-class region capacity
#define IT   64      // i-tile for KB (= block size: 1 thread per i-row)
#define JT   16      // j-tile rows staged in smem (RATIO = IT/JT = 4)
#define RATIO 4
#define NB3  888     // KB grid (6 per SM, one wave)
#define KAB  128     // KA blocks (128 x 128 = 16384 threads)

// ---- device scratch ----
__device__ float g_cf[8 * CAP * DIM];    // class-region normalized feats
__device__ int   g_fill[NC] = {0, 0, CAP, 2*CAP, 3*CAP, 4*CAP, 5*CAP, 6*CAP, 7*CAP};
__device__ float g_sum[NC * DIM];        // per-class normalized-feature sums
__device__ float g_cross[NC * NC];       // UNORDERED relu(dot) sums per class pair
__device__ unsigned g_t3;

// ---- KA: fused classify + normalize + scatter ----
__global__ void __launch_bounds__(128) ka_classify_scatter(
        const int* __restrict__ labels,
        const float* __restrict__ feats,
        const float* __restrict__ scores) {
    int tid = threadIdx.x;
    int lane = tid & 31;
    int p = blockIdx.x * 128 + tid;

    const float* sr = scores + p * NC;
    float sv[NC];
    #pragma unroll
    for (int c = 0; c < NC; c++) sv[c] = __ldg(&sr[c]);
    float mv = sv[0]; int mi = 0;
    #pragma unroll
    for (int c = 1; c < NC; c++) if (sv[c] > mv) { mv = sv[c]; mi = c; }
    float e = 0.f;
    #pragma unroll
    for (int c = 0; c < NC; c++) e += expf(sv[c] - mv);
    float pmax = 1.0f / e;

    int lab = labels[p];
    int cls = (lab == mi && pmax >= 0.5f && lab >= 1) ? lab : 0;

    unsigned bal = __ballot_sync(0xffffffffu, cls > 0);
    while (bal) {
        int src = __ffs(bal) - 1;
        bal &= bal - 1;
        int pc = __shfl_sync(0xffffffffu, cls, src);
        int pp = __shfl_sync(0xffffffffu, p, src);

        float x0 = feats[pp * DIM + lane];
        float x1 = feats[pp * DIM + 32 + lane];
        float ss = x0 * x0 + x1 * x1;
        #pragma unroll
        for (int o = 16; o > 0; o >>= 1) ss += __shfl_xor_sync(0xffffffffu, ss, o);
        float inv = 1.0f / fmaxf(sqrtf(ss), 1e-12f);
        float f0 = x0 * inv, f1 = x1 * inv;

        int slot;
        if (lane == 0) slot = atomicAdd(&g_fill[pc], 1);
        slot = __shfl_sync(0xffffffffu, slot, 0);

        g_cf[slot * DIM + lane]      = f0;
        g_cf[slot * DIM + 32 + lane] = f1;
        atomicAdd(&g_sum[pc * DIM + lane],      f0);
        atomicAdd(&g_sum[pc * DIM + 32 + lane], f1);
    }
}

// ---- KB: triangular pairwise relu(dot); 64-thread blocks, small jobs ----
__global__ void __launch_bounds__(64, 6) kb_pairs(float* __restrict__ out) {
    __shared__ float4 Js[JT][17];      // pitch 17: conflict-free
    __shared__ float  scross[NC * NC];
    __shared__ int    s_pre[NC + 1];
    __shared__ int    s_base[NC];
    __shared__ int    jphys[JT];

    int tid = threadIdx.x;
    for (int i = tid; i < NC * NC; i += 64) scross[i] = 0.f;
    if (tid == 0) {
        int acc = 0;
        #pragma unroll
        for (int c = 1; c < NC; c++) {
            int base = (c - 1) * CAP;
            s_base[c] = base;
            s_pre[c] = acc;
            acc += g_fill[c] - base;
        }
        s_pre[NC] = acc;
    }
    __syncthreads();

    int nv = s_pre[NC];
    int nit = (nv + IT - 1) / IT;
    int njt = (nv + JT - 1) / JT;
    // triangular job set: (it, jt) with jt >= RATIO*it
    int njobs = nit * njt - RATIO * nit * (nit - 1) / 2;

    const float4* cf4 = (const float4*)g_cf;

    for (int job = blockIdx.x; job < njobs; job += NB3) {
        int it = 0, rem = job;
        while (rem >= njt - RATIO * it) { rem -= njt - RATIO * it; it++; }
        int jt = RATIO * it + rem;
        int jb = jt * JT;

        int iv = it * IT + tid;
        int ci = 0, iphys = 0;
        {
            int c = 1;
            #pragma unroll
            for (int cc = 2; cc < NC; cc++) if (iv >= s_pre[cc]) c = cc;
            iphys = s_base[c] + (iv - s_pre[c]);
            ci = (iv < nv) ? c : 0;
        }
        float4 row[16];
        #pragma unroll
        for (int c4 = 0; c4 < 16; c4++) row[c4] = cf4[iphys * 16 + c4];

        int jmin = iv - jb;   // count local j only if j > jmin

        __syncthreads();
        if (tid < JT) {
            int jv = jb + tid;
            int c = 1;
            #pragma unroll
            for (int cc = 2; cc < NC; cc++) if (jv >= s_pre[cc]) c = cc;
            jphys[tid] = (jv < nv) ? (s_base[c] + (jv - s_pre[c])) : 0;
        }
        __syncthreads();
        #pragma unroll
        for (int q0 = 0; q0 < JT * 16; q0 += 64) {
            int q = q0 + tid;
            Js[q >> 4][q & 15] = cf4[jphys[q >> 4] * 16 + (q & 15)];
        }
        __syncthreads();

        if (ci > 0) {
            #pragma unroll
            for (int c = 1; c < NC; c++) {
                if (c == ci) continue;
                int rs = max(s_pre[c] - jb, 0);
                int re = min(s_pre[c + 1] - jb, JT);
                if (rs >= re) continue;
                float rsum = 0.f;
                int j = rs;
                for (; j + 1 < re; j += 2) {
                    float d0x = 0.f, d0y = 0.f, d0z = 0.f, d0w = 0.f;
                    float d1x = 0.f, d1y = 0.f, d1z = 0.f, d1w = 0.f;
                    #pragma unroll
                    for (int c4 = 0; c4 < 16; c4++) {
                        float4 b0 = Js[j][c4];
                        float4 b1 = Js[j + 1][c4];
                        d0x += row[c4].x * b0.x; d0y += row[c4].y * b0.y;
                        d0z += row[c4].z * b0.z; d0w += row[c4].w * b0.w;
                        d1x += row[c4].x * b1.x; d1y += row[c4].y * b1.y;
                        d1z += row[c4].z * b1.z; d1w += row[c4].w * b1.w;
                    }
                    float s0 = fmaxf((d0x + d0y) + (d0z + d0w), 0.f);
                    float s1 = fmaxf((d1x + d1y) + (d1z + d1w), 0.f);
                    if (j > jmin)     rsum += s0;
                    if (j + 1 > jmin) rsum += s1;
                }
                if (j < re) {
                    float dx = 0.f, dy = 0.f, dz = 0.f, dw = 0.f;
                    #pragma unroll
                    for (int c4 = 0; c4 < 16; c4++) {
                        float4 b = Js[j][c4];
                        dx += row[c4].x * b.x; dy += row[c4].y * b.y;
                        dz += row[c4].z * b.z; dw += row[c4].w * b.w;
                    }
                    if (j > jmin) rsum += fmaxf((dx + dy) + (dz + dw), 0.f);
                }
                if (rsum > 0.f) {
                    int lo = min(ci, c), hi = max(ci, c);
                    atomicAdd(&scross[lo * NC + hi], rsum);
                }
            }
        }
    }
    __syncthreads();
    for (int i = tid; i < NC * NC; i += 64)
        if (scross[i] != 0.f) atomicAdd(&g_cross[i], scross[i]);

    // ---- last-block finalize + reset for next graph replay ----
    __shared__ bool is_last;
    __threadfence();
    __syncthreads();
    if (tid == 0) is_last = (atomicAdd(&g_t3, 1u) == NB3 - 1);
    __syncthreads();
    if (!is_last) return;
    __threadfence();

    __shared__ float red[64];
    float acc = 0.f;
    if (tid >= 1 && tid < NC) {
        float cnt = (float)(s_pre[tid + 1] - s_pre[tid]);
        float quad = 0.f;
        #pragma unroll
        for (int d = 0; d < DIM; d++) {
            float vv = g_sum[tid * DIM + d];
            quad += vv * vv;
        }
        float npairs = cnt * (cnt - 1.0f) * 0.5f;
        if (npairs > 0.f)
            acc += 1.0f - ((quad - cnt) * 0.5f) / npairs;
    }
    for (int idx = tid; idx < NC * NC; idx += 64) {
        int a = idx / NC, b = idx % NC;
        if (a >= 1 && b > a) {
            float ca = (float)(s_pre[a + 1] - s_pre[a]);
            float cb = (float)(s_pre[b + 1] - s_pre[b]);
            float den = ca * cb;
            if (den > 0.f) acc += g_cross[a * NC + b] / den;
        }
    }
    red[tid] = acc;
    __syncthreads();
    #pragma unroll
    for (int o = 32; o > 0; o >>= 1) {
        if (tid < o) red[tid] += red[tid + o];
        __syncthreads();
    }
    if (tid == 0) out[0] = red[0];

    // reset for next replay
    __syncthreads();
    if (tid >= 1 && tid < NC) g_fill[tid] = (tid - 1) * CAP;
    for (int i = tid; i < NC * NC; i += 64) g_cross[i] = 0.f;
    for (int i = tid; i < NC * DIM; i += 64) g_sum[i] = 0.f;
    if (tid == 0) g_t3 = 0;
}

extern "C" void kernel_launch(void* const* d_in, const int* in_sizes, int n_in,
                              void* d_out, int out_size) {
    const int*   labels = nullptr;
    const float* feats  = nullptr;
    const float* scores = nullptr;
    for (int i = 0; i < n_in; i++) {
        if (in_sizes[i] == NPTS)            labels = (const int*)d_in[i];
        else if (in_sizes[i] == NPTS * DIM) feats  = (const float*)d_in[i];
        else if (in_sizes[i] == NPTS * NC)  scores = (const float*)d_in[i];
    }
    float* out = (float*)d_out;

    ka_classify_scatter<<<KAB, 128>>>(labels, feats, scores);
    kb_pairs<<<NB3, 64>>>(out);
}

// round 12
// speedup vs baseline: 1.3330x; 1.0021x over previous
#include <cuda_runtime.h>
#include <math.h>

#define NPTS 16384
#define DIM  64
#define NC   9
#define CAP  16384   // per-class region capacity
#define IT   64      // i-tile (= block size: 1 thread per i-row)
#define JT   32      // j-tile rows staged in smem
#define NB3  592     // KB grid (one wave, >= njobs)
#define KAB  128     // KA blocks

typedef unsigned long long u64;

// packed f32x2 fma: acc = a*b + acc (elementwise on 2 packed floats)
#define FMA2(acc, a, b) \
    asm("fma.rn.f32x2 %0, %1, %2, %3;" : "=l"(acc) : "l"(a), "l"(b), "l"(acc))

__device__ __forceinline__ float sum2(u64 v) {
    float2 f = *(float2*)&v;
    return f.x + f.y;
}

// ---- device scratch ----
__device__ float g_cf[8 * CAP * DIM];    // class-region normalized feats
__device__ int   g_fill[NC] = {0, 0, CAP, 2*CAP, 3*CAP, 4*CAP, 5*CAP, 6*CAP, 7*CAP};
__device__ float g_sum[NC * DIM];        // per-class normalized-feature sums
__device__ float g_cross[NC * NC];       // UNORDERED relu(dot) sums per class pair
__device__ unsigned g_t3;

// ---- KA: fused classify + normalize + scatter ----
__global__ void __launch_bounds__(128) ka_classify_scatter(
        const int* __restrict__ labels,
        const float* __restrict__ feats,
        const float* __restrict__ scores) {
    int tid = threadIdx.x;
    int lane = tid & 31;
    int p = blockIdx.x * 128 + tid;

    const float* sr = scores + p * NC;
    float sv[NC];
    #pragma unroll
    for (int c = 0; c < NC; c++) sv[c] = __ldg(&sr[c]);
    float mv = sv[0]; int mi = 0;
    #pragma unroll
    for (int c = 1; c < NC; c++) if (sv[c] > mv) { mv = sv[c]; mi = c; }
    float e = 0.f;
    #pragma unroll
    for (int c = 0; c < NC; c++) e += expf(sv[c] - mv);
    float pmax = 1.0f / e;

    int lab = labels[p];
    int cls = (lab == mi && pmax >= 0.5f && lab >= 1) ? lab : 0;

    unsigned bal = __ballot_sync(0xffffffffu, cls > 0);
    while (bal) {
        int src = __ffs(bal) - 1;
        bal &= bal - 1;
        int pc = __shfl_sync(0xffffffffu, cls, src);
        int pp = __shfl_sync(0xffffffffu, p, src);

        float x0 = feats[pp * DIM + lane];
        float x1 = feats[pp * DIM + 32 + lane];
        float ss = x0 * x0 + x1 * x1;
        #pragma unroll
        for (int o = 16; o > 0; o >>= 1) ss += __shfl_xor_sync(0xffffffffu, ss, o);
        float inv = 1.0f / fmaxf(sqrtf(ss), 1e-12f);
        float f0 = x0 * inv, f1 = x1 * inv;

        int slot;
        if (lane == 0) slot = atomicAdd(&g_fill[pc], 1);
        slot = __shfl_sync(0xffffffffu, slot, 0);

        g_cf[slot * DIM + lane]      = f0;
        g_cf[slot * DIM + 32 + lane] = f1;
        atomicAdd(&g_sum[pc * DIM + lane],      f0);
        atomicAdd(&g_sum[pc * DIM + 32 + lane], f1);
    }
}

// ---- KB: triangular pairwise relu(dot) with packed f32x2 FMA ----
__global__ void __launch_bounds__(64, 6) kb_pairs(float* __restrict__ out) {
    __shared__ ulonglong2 Js[JT][17];   // pitch 17: conflict-free, 16B aligned
    __shared__ float  scross[NC * NC];
    __shared__ int    s_pre[NC + 1];
    __shared__ int    s_base[NC];
    __shared__ int    jphys[JT];

    int tid = threadIdx.x;
    for (int i = tid; i < NC * NC; i += 64) scross[i] = 0.f;
    if (tid == 0) {
        int acc = 0;
        #pragma unroll
        for (int c = 1; c < NC; c++) {
            int base = (c - 1) * CAP;
            s_base[c] = base;
            s_pre[c] = acc;
            acc += g_fill[c] - base;
        }
        s_pre[NC] = acc;
    }
    __syncthreads();

    int nv = s_pre[NC];
    int nit = (nv + IT - 1) / IT;
    int njt = (nv + JT - 1) / JT;
    // job (it, jt) needed iff jt >= jt_min(it) = (it*IT)/JT = 2*it
    int njobs = nit * njt - nit * (nit - 1);

    const ulonglong2* cfp = (const ulonglong2*)g_cf;   // 16 per row

    for (int job = blockIdx.x; job < njobs; job += NB3) {
        int it = 0, rem = job;
        while (rem >= njt - 2 * it) { rem -= njt - 2 * it; it++; }
        int jt = 2 * it + rem;
        int jb = jt * JT;

        int iv = it * IT + tid;
        int ci = 0, iphys = 0;
        {
            int c = 1;
            #pragma unroll
            for (int cc = 2; cc < NC; cc++) if (iv >= s_pre[cc]) c = cc;
            iphys = s_base[c] + (iv - s_pre[c]);
            ci = (iv < nv) ? c : 0;
        }
        // i-row in registers as 32 packed f32x2
        u64 rowp[32];
        #pragma unroll
        for (int c4 = 0; c4 < 16; c4++) {
            ulonglong2 t = cfp[iphys * 16 + c4];
            rowp[2 * c4]     = t.x;
            rowp[2 * c4 + 1] = t.y;
        }

        int jmin = iv - jb;   // count local j only if j > jmin

        __syncthreads();
        if (tid < JT) {
            int jv = jb + tid;
            int c = 1;
            #pragma unroll
            for (int cc = 2; cc < NC; cc++) if (jv >= s_pre[cc]) c = cc;
            jphys[tid] = (jv < nv) ? (s_base[c] + (jv - s_pre[c])) : 0;
        }
        __syncthreads();
        #pragma unroll
        for (int q0 = 0; q0 < JT * 16; q0 += 64) {
            int q = q0 + tid;
            Js[q >> 4][q & 15] = cfp[jphys[q >> 4] * 16 + (q & 15)];
        }
        __syncthreads();

        if (ci > 0) {
            #pragma unroll
            for (int c = 1; c < NC; c++) {
                if (c == ci) continue;
                int rs = max(s_pre[c] - jb, 0);
                int re = min(s_pre[c + 1] - jb, JT);
                if (rs >= re) continue;
                float rsum = 0.f;
                int j = rs;
                for (; j + 1 < re; j += 2) {
                    u64 a0 = 0ull, a1 = 0ull, b0 = 0ull, b1 = 0ull;
                    #pragma unroll
                    for (int c4 = 0; c4 < 16; c4++) {
                        ulonglong2 p = Js[j][c4];
                        ulonglong2 q = Js[j + 1][c4];
                        FMA2(a0, rowp[2 * c4],     p.x);
                        FMA2(a1, rowp[2 * c4 + 1], p.y);
                        FMA2(b0, rowp[2 * c4],     q.x);
                        FMA2(b1, rowp[2 * c4 + 1], q.y);
                    }
                    float s0 = fmaxf(sum2(a0) + sum2(a1), 0.f);
                    float s1 = fmaxf(sum2(b0) + sum2(b1), 0.f);
                    if (j > jmin)     rsum += s0;
                    if (j + 1 > jmin) rsum += s1;
                }
                if (j < re) {
                    u64 a0 = 0ull, a1 = 0ull;
                    #pragma unroll
                    for (int c4 = 0; c4 < 16; c4++) {
                        ulonglong2 p = Js[j][c4];
                        FMA2(a0, rowp[2 * c4],     p.x);
                        FMA2(a1, rowp[2 * c4 + 1], p.y);
                    }
                    if (j > jmin) rsum += fmaxf(sum2(a0) + sum2(a1), 0.f);
                }
                if (rsum > 0.f) {
                    int lo = min(ci, c), hi = max(ci, c);
                    atomicAdd(&scross[lo * NC + hi], rsum);
                }
            }
        }
    }
    __syncthreads();
    for (int i = tid; i < NC * NC; i += 64)
        if (scross[i] != 0.f) atomicAdd(&g_cross[i], scross[i]);

    // ---- last-block finalize + reset for next graph replay ----
    __shared__ bool is_last;
    __threadfence();
    __syncthreads();
    if (tid == 0) is_last = (atomicAdd(&g_t3, 1u) == NB3 - 1);
    __syncthreads();
    if (!is_last) return;
    __threadfence();

    __shared__ float red[64];
    float acc = 0.f;
    if (tid >= 1 && tid < NC) {
        float cnt = (float)(s_pre[tid + 1] - s_pre[tid]);
        float quad = 0.f;
        #pragma unroll
        for (int d = 0; d < DIM; d++) {
            float vv = g_sum[tid * DIM + d];
            quad += vv * vv;
        }
        float npairs = cnt * (cnt - 1.0f) * 0.5f;
        if (npairs > 0.f)
            acc += 1.0f - ((quad - cnt) * 0.5f) / npairs;
    }
    for (int idx = tid; idx < NC * NC; idx += 64) {
        int a = idx / NC, b = idx % NC;
        if (a >= 1 && b > a) {
            float ca = (float)(s_pre[a + 1] - s_pre[a]);
            float cb = (float)(s_pre[b + 1] - s_pre[b]);
            float den = ca * cb;
            if (den > 0.f) acc += g_cross[a * NC + b] / den;
        }
    }
    red[tid] = acc;
    __syncthreads();
    #pragma unroll
    for (int o = 32; o > 0; o >>= 1) {
        if (tid < o) red[tid] += red[tid + o];
        __syncthreads();
    }
    if (tid == 0) out[0] = red[0];

    // reset for next replay
    __syncthreads();
    if (tid >= 1 && tid < NC) g_fill[tid] = (tid - 1) * CAP;
    for (int i = tid; i < NC * NC; i += 64) g_cross[i] = 0.f;
    for (int i = tid; i < NC * DIM; i += 64) g_sum[i] = 0.f;
    if (tid == 0) g_t3 = 0;
}

extern "C" void kernel_launch(void* const* d_in, const int* in_sizes, int n_in,
                              void* d_out, int out_size) {
    const int*   labels = nullptr;
    const float* feats  = nullptr;
    const float* scores = nullptr;
    for (int i = 0; i < n_in; i++) {
        if (in_sizes[i] == NPTS)            labels = (const int*)d_in[i];
        else if (in_sizes[i] == NPTS * DIM) feats  = (const float*)d_in[i];
        else if (in_sizes[i] == NPTS * NC)  scores = (const float*)d_in[i];
    }
    float* out = (float*)d_out;

    ka_classify_scatter<<<KAB, 128>>>(labels, feats, scores);
    kb_pairs<<<NB3, 64>>>(out);
}